// round 11
// baseline (speedup 1.0000x reference)
#include <cuda_runtime.h>
#include <cuda_fp16.h>
#include <mma.h>
#include <cstdint>
#include <cstddef>

using namespace nvcuda;

#define NN   16384
#define DF   256
#define KCAT 512
#define BM   112          // 7*16 -> 147 CTAs = 1 full wave on 148 SMs

// ---------------- device-global scratch ----------------
__device__ __half g_ftT[(size_t)DF * NN];    // features^T fp16 [256][16384]
__device__ __half g_cat[(size_t)NN * KCAT];  // [features | neigh] fp16 [16384][512]
__device__ __half g_w[(size_t)DF * KCAT];    // W fp16 [256][512]

// ---------------- k_main smem (fp16, BK=64, BM=112) ----------------
constexpr int ASTM = 72;                       // row stride (halves) = 144 B
constexpr int A_STG = BM * ASTM * 2;           // 16128 B
constexpr int B_STG = 256 * ASTM * 2;          // 36864 B
constexpr int OFF_BM = 2 * A_STG;              // 32256
constexpr int OFF_SROW = OFF_BM + 3 * B_STG;   // 142848
constexpr int SMEM_MAIN = OFF_SROW + 512;      // 143360

// ---------------- k_out smem: 4-stage, BK=32 (frozen R9) ----------------
constexpr int AST = 40;
constexpr int AO_STG = 128 * AST * 2;          // 10240
constexpr int BO_STG = 256 * AST * 2;          // 20480
constexpr int OFF_BO = 4 * AO_STG;             // 40960
constexpr int SST = 68;
constexpr int SMEM_OUT = OFF_BO + 4 * BO_STG + 512;  // 123392

__device__ __forceinline__ uint32_t smem_u32(const void* p) {
    uint32_t a;
    asm("{ .reg .u64 t; cvta.to.shared.u64 t, %1; cvt.u32.u64 %0, t; }" : "=r"(a) : "l"(p));
    return a;
}
__device__ __forceinline__ void cpa16(uint32_t saddr, const void* g) {
    asm volatile("cp.async.cg.shared.global [%0], [%1], 16;" :: "r"(saddr), "l"(g));
}
__device__ __forceinline__ void cpa_commit() { asm volatile("cp.async.commit_group;" ::: "memory"); }
__device__ __forceinline__ void cpa_wait0()  { asm volatile("cp.async.wait_group 0;" ::: "memory"); }
__device__ __forceinline__ void cpa_wait1()  { asm volatile("cp.async.wait_group 1;" ::: "memory"); }
__device__ __forceinline__ void cpa_wait2()  { asm volatile("cp.async.wait_group 2;" ::: "memory"); }

// ---------------- prep ----------------
__global__ void __launch_bounds__(256) k_prep(const float* __restrict__ f) {
    __shared__ float t[32][33];
    int n0 = blockIdx.x * 32, d0 = blockIdx.y * 32;
    int tx = threadIdx.x, ty = threadIdx.y;
    #pragma unroll
    for (int i = ty; i < 32; i += 8) {
        float v = f[(size_t)(n0 + i) * DF + d0 + tx];
        t[i][tx] = v;
        g_cat[(size_t)(n0 + i) * KCAT + d0 + tx] = __float2half(v);
    }
    __syncthreads();
    #pragma unroll
    for (int i = ty; i < 32; i += 8)
        g_ftT[(size_t)(d0 + i) * NN + n0 + tx] = __float2half(t[tx][i]);
}

__global__ void __launch_bounds__(256) k_wconv(const float* __restrict__ W, int base) {
    int i = base + blockIdx.x * 256 + threadIdx.x;
    g_w[i] = __float2half(W[i]);
}

// ================= k_main: fp16 HMMA, BM=112, 448 threads (14 warps, 7x2, 16x128 tiles) =================
__global__ void __launch_bounds__(448, 1) k_main(const float* __restrict__ adj) {
    extern __shared__ char sm[];
    __half* Abuf = (__half*)sm;                // [2][112][72]
    __half* Bbuf = (__half*)(sm + OFF_BM);     // [3][256][72]
    float*  srow = (float*)(sm + OFF_SROW);    // [112]
    __half* hstage = (__half*)sm;              // epilogue reuse [112][72]

    const int tid = threadIdx.x;
    const int lane = tid & 31;
    const int wid = tid >> 5;                  // 0..13
    const int wm = wid >> 1, wn = wid & 1;     // 7 x 2 warp grid, 16x128 warp tiles
    const int m0 = blockIdx.x * BM;
    const uint32_t b_u32 = smem_u32(Bbuf);

    wmma::fragment<wmma::accumulator, 16, 16, 16, __half> acc[8];
    #pragma unroll
    for (int ni = 0; ni < 8; ni++)
        wmma::fill_fragment(acc[ni], __float2half(0.0f));

    float rowacc[4] = {0.f, 0.f, 0.f, 0.f};
    float4 va[4];

    auto ldgA = [&](int it) {
        int k0 = it * 64;
        #pragma unroll
        for (int j = 0; j < 4; j++) {          // 112 rows x 16 float4 = 1792 = 448*4
            int idx = tid + j * 448;
            int row = idx >> 4, c4 = idx & 15;
            int grow = m0 + row;
            if (grow >= NN) grow = NN - 1;     // ragged last tile: clamp (no OOB; result discarded)
            va[j] = *(const float4*)(adj + (size_t)grow * NN + k0 + c4 * 4);
        }
    };
    auto stsA = [&](int buf) {
        __half* At = Abuf + buf * BM * ASTM;
        #pragma unroll
        for (int j = 0; j < 4; j++) {
            int idx = tid + j * 448;
            int row = idx >> 4, c4 = idx & 15;
            float4 v = va[j];
            rowacc[j] += (v.x + v.y) + (v.z + v.w);
            __half2 h0 = __floats2half2_rn(v.x, v.y);
            __half2 h1 = __floats2half2_rn(v.z, v.w);
            uint2 u;
            u.x = *(uint32_t*)&h0;
            u.y = *(uint32_t*)&h1;
            *(uint2*)(At + row * ASTM + c4 * 4) = u;
        }
    };
    auto cpaB = [&](int buf, int it) {
        int k0 = it * 64;
        uint32_t b0 = b_u32 + buf * B_STG;
        #pragma unroll
        for (int j = 0; j < 5; j++) {          // 256 rows x 8 x 16B = 2048 chunks
            int idx = tid + j * 448;
            if (idx < 2048) {
                int row = idx >> 3, c16 = idx & 7;
                cpa16(b0 + (row * ASTM + c16 * 8) * 2, g_ftT + (size_t)row * NN + k0 + c16 * 8);
            }
        }
    };

    // ---- prologue ----
    ldgA(0);
    stsA(0);
    ldgA(1);
    cpaB(0, 0); cpa_commit();
    cpaB(1, 1); cpa_commit();

    constexpr int NK = NN / 64;  // 256
    int bs = 0, bs2 = 2;

    #pragma unroll 1
    for (int it = 0; it < NK; ++it) {
        int cur = it & 1;
        cpa_wait1();       // B(it) arrived
        __syncthreads();   // A(it)+B(it) visible; prior reads of A[cur^1], B[bs2] done

        if (it + 1 < NK) stsA(cur ^ 1);
        if (it + 2 < NK) {
            ldgA(it + 2);
            cpaB(bs2, it + 2);
        }
        cpa_commit();

        const __half* At = Abuf + cur * BM * ASTM;
        const __half* Bt = Bbuf + bs * 256 * ASTM;
        #pragma unroll
        for (int ks = 0; ks < 4; ++ks) {
            wmma::fragment<wmma::matrix_a, 16, 16, 16, __half, wmma::row_major> af;
            wmma::load_matrix_sync(af, At + (wm * 16) * ASTM + ks * 16, ASTM);
            #pragma unroll
            for (int ni = 0; ni < 8; ni++) {
                wmma::fragment<wmma::matrix_b, 16, 16, 16, __half, wmma::col_major> bf;
                wmma::load_matrix_sync(bf, Bt + (wn * 128 + ni * 16) * ASTM + ks * 16, ASTM);
                wmma::mma_sync(acc[ni], af, bf, acc[ni]);
            }
        }
        bs = (bs == 2) ? 0 : bs + 1;
        bs2 = (bs2 == 2) ? 0 : bs2 + 1;
    }
    cpa_wait0();

    // exact fp32 rowsum -> 1/(deg+1); 16 lanes share a row
    #pragma unroll
    for (int j = 0; j < 4; j++) {
        float s = rowacc[j];
        s += __shfl_xor_sync(0xFFFFFFFFu, s, 1);
        s += __shfl_xor_sync(0xFFFFFFFFu, s, 2);
        s += __shfl_xor_sync(0xFFFFFFFFu, s, 4);
        s += __shfl_xor_sync(0xFFFFFFFFu, s, 8);
        int row = (tid + j * 448) >> 4;
        if ((lane & 15) == 0) srow[row] = 1.0f / (s + 1.0f);
    }
    __syncthreads();  // all MMA done; stage may overwrite Abuf

    // epilogue: 4 passes of 64 cols through half staging
    // frag ni of warp (wm, wn) holds rows [wm*16,+16), cols wn*128 + ni*16
    #pragma unroll 1
    for (int p = 0; p < 4; p++) {
        if (wn == (p >> 1)) {
            int nbase = (p & 1) * 4;
            #pragma unroll
            for (int q = 0; q < 4; q++)
                wmma::store_matrix_sync(hstage + (wm * 16) * ASTM + q * 16,
                                        acc[nbase + q], ASTM, wmma::mem_row_major);
        }
        __syncthreads();
        #pragma unroll
        for (int j = 0; j < 16; j++) {         // 112*64 = 7168 = 448*16
            int idx = tid + j * 448;
            int r = idx >> 6, c = idx & 63;
            if (m0 + r < NN) {
                float v = __half2float(hstage[r * ASTM + c]) * srow[r];
                g_cat[(size_t)(m0 + r) * KCAT + 256 + p * 64 + c] = __float2half(v);
            }
        }
        __syncthreads();
    }
}

// ================= k_out: fp16, 4-stage pipeline (frozen R9) =================
__global__ void __launch_bounds__(512, 1) k_out(float* __restrict__ out) {
    extern __shared__ char sm[];
    __half* Abuf = (__half*)sm;                // [4][128][40]
    __half* Bbuf = (__half*)(sm + OFF_BO);     // [4][256][40]
    float*  stage = (float*)sm;                // epilogue reuse [128][68]

    const int tid = threadIdx.x;
    const int wid = tid >> 5;
    const int wm = wid >> 2, wn = wid & 3;
    const int m0 = blockIdx.x * 128;
    const uint32_t a_u32 = smem_u32(Abuf);
    const uint32_t b_u32 = smem_u32(Bbuf);

    wmma::fragment<wmma::accumulator, 16, 16, 16, float> acc[2][4];
    #pragma unroll
    for (int mi = 0; mi < 2; mi++)
        #pragma unroll
        for (int ni = 0; ni < 4; ni++)
            wmma::fill_fragment(acc[mi][ni], 0.0f);

    auto loadTile = [&](int slot, int it) {
        int k0 = it * 32;
        uint32_t a0 = a_u32 + slot * AO_STG;
        uint32_t b0 = b_u32 + slot * BO_STG;
        {
            int row = tid >> 2, c8 = tid & 3;
            cpa16(a0 + (row * AST + c8 * 8) * 2, g_cat + (size_t)(m0 + row) * KCAT + k0 + c8 * 8);
        }
        #pragma unroll
        for (int j = 0; j < 2; j++) {
            int idx = tid + j * 512;
            int row = idx >> 2, c8 = idx & 3;
            cpa16(b0 + (row * AST + c8 * 8) * 2, g_w + (size_t)row * KCAT + k0 + c8 * 8);
        }
    };

    loadTile(0, 0); cpa_commit();
    loadTile(1, 1); cpa_commit();
    loadTile(2, 2); cpa_commit();

    constexpr int NK = KCAT / 32;  // 16
    #pragma unroll 1
    for (int it = 0; it < NK; ++it) {
        int cur = it & 3;
        cpa_wait2();
        __syncthreads();

        if (it + 3 < NK) { loadTile((it + 3) & 3, it + 3); cpa_commit(); }

        const __half* At = Abuf + cur * 128 * AST;
        const __half* Bt = Bbuf + cur * 256 * AST;
        #pragma unroll
        for (int ks = 0; ks < 2; ++ks) {
            wmma::fragment<wmma::matrix_a, 16, 16, 16, __half, wmma::row_major> af[2];
            #pragma unroll
            for (int mi = 0; mi < 2; mi++)
                wmma::load_matrix_sync(af[mi], At + (wm * 32 + mi * 16) * AST + ks * 16, AST);
            #pragma unroll
            for (int ni = 0; ni < 4; ni++) {
                wmma::fragment<wmma::matrix_b, 16, 16, 16, __half, wmma::col_major> bf;
                wmma::load_matrix_sync(bf, Bt + (wn * 64 + ni * 16) * AST + ks * 16, AST);
                #pragma unroll
                for (int mi = 0; mi < 2; mi++)
                    wmma::mma_sync(acc[mi][ni], af[mi], bf, acc[mi][ni]);
            }
        }
    }
    cpa_wait0();
    __syncthreads();

    #pragma unroll 1
    for (int p = 0; p < 4; p++) {
        if (wn == p) {
            #pragma unroll
            for (int mi = 0; mi < 2; mi++)
                #pragma unroll
                for (int ni = 0; ni < 4; ni++)
                    wmma::store_matrix_sync(stage + (wm * 32 + mi * 16) * SST + ni * 16,
                                            acc[mi][ni], SST, wmma::mem_row_major);
        }
        __syncthreads();
        #pragma unroll
        for (int j = 0; j < 16; j++) {
            int idx = tid + j * 512;
            int r = idx >> 6, c = idx & 63;
            out[(size_t)(m0 + r) * DF + p * 64 + c] = stage[r * SST + c];
        }
        __syncthreads();
    }
}

// ---------------- launch ----------------
extern "C" void kernel_launch(void* const* d_in, const int* in_sizes, int n_in,
                              void* d_out, int out_size) {
    const float* features = nullptr;
    const float* adj = nullptr;
    const float* W = nullptr;
    for (int i = 0; i < n_in; i++) {
        if (in_sizes[i] == NN * NN) adj = (const float*)d_in[i];
        else if (in_sizes[i] == NN * DF) features = (const float*)d_in[i];
        else if (in_sizes[i] == DF * KCAT) W = (const float*)d_in[i];
    }
    float* out = (float*)d_out;

    cudaFuncSetAttribute(k_main, cudaFuncAttributeMaxDynamicSharedMemorySize, SMEM_MAIN);
    cudaFuncSetAttribute(k_out,  cudaFuncAttributeMaxDynamicSharedMemorySize, SMEM_OUT);

    const int n_tiles = (NN + BM - 1) / BM;  // 147

    // k_main stays at launch index 3 (ncu capture slot)
    k_prep<<<dim3(NN / 32, DF / 32), dim3(32, 8)>>>(features);
    k_wconv<<<(DF * KCAT / 2) / 256, 256>>>(W, 0);
    k_wconv<<<(DF * KCAT / 2) / 256, 256>>>(W, DF * KCAT / 2);
    k_main<<<n_tiles, 448, SMEM_MAIN>>>(adj);
    k_out<<<NN / 128, 512, SMEM_OUT>>>(out);
}

// round 12
// speedup vs baseline: 1.2809x; 1.2809x over previous
#include <cuda_runtime.h>
#include <cuda_fp16.h>
#include <mma.h>
#include <cstdint>
#include <cstddef>

using namespace nvcuda;

#define NN   16384
#define DF   256
#define KCAT 512

// ---------------- device-global scratch ----------------
__device__ __half g_ftT[(size_t)DF * NN];    // features^T fp16 [256][16384]
__device__ __half g_cat[(size_t)NN * KCAT];  // cols 0..255 = features fp16 (neigh half unused)
__device__ __half g_w[(size_t)DF * KCAT];    // W fp16 [256][512]

// ---------------- k_main smem layout ----------------
// mainloop: A [2][128][72]h @0 (36864) ; B [3][256][72]h @36864 (110592) -> ends 147456
// tail:     Nbuf [128][264]h @0 (67584) ; A-out [4][128][40]h @68096 (40960)
//           B-out [4][256][40]h @109056 (81920) -> ends 190976 ; srow @190976
constexpr int ASTM = 72;
constexpr int A_STG = 128 * ASTM * 2;          // 18432
constexpr int B_STG = 256 * ASTM * 2;          // 36864
constexpr int OFF_BM = 2 * A_STG;              // 36864

constexpr int ASTN = 264;                      // Nbuf stride (halves); 528B rows, LDSM conflict-free
constexpr int AST  = 40;                       // out-GEMM A/B stage stride (halves)
constexpr int AO_STG = 128 * AST * 2;          // 10240
constexpr int BO_STG = 256 * AST * 2;          // 20480
constexpr int OFF_AO = 68096;
constexpr int OFF_BO = OFF_AO + 4 * AO_STG;    // 109056
constexpr int OFF_SROW = OFF_BO + 4 * BO_STG;  // 190976
constexpr int SST = 68;                        // f32 epilogue stage stride (reuses A-out region)
constexpr int SMEM_MAIN = OFF_SROW + 512;      // 191488

__device__ __forceinline__ uint32_t smem_u32(const void* p) {
    uint32_t a;
    asm("{ .reg .u64 t; cvta.to.shared.u64 t, %1; cvt.u32.u64 %0, t; }" : "=r"(a) : "l"(p));
    return a;
}
__device__ __forceinline__ void cpa16(uint32_t saddr, const void* g) {
    asm volatile("cp.async.cg.shared.global [%0], [%1], 16;" :: "r"(saddr), "l"(g));
}
__device__ __forceinline__ void cpa_commit() { asm volatile("cp.async.commit_group;" ::: "memory"); }
__device__ __forceinline__ void cpa_wait0()  { asm volatile("cp.async.wait_group 0;" ::: "memory"); }
__device__ __forceinline__ void cpa_wait1()  { asm volatile("cp.async.wait_group 1;" ::: "memory"); }
__device__ __forceinline__ void cpa_wait2()  { asm volatile("cp.async.wait_group 2;" ::: "memory"); }

// ---------------- prep ----------------
__global__ void __launch_bounds__(256) k_prep(const float* __restrict__ f) {
    __shared__ float t[32][33];
    int n0 = blockIdx.x * 32, d0 = blockIdx.y * 32;
    int tx = threadIdx.x, ty = threadIdx.y;
    #pragma unroll
    for (int i = ty; i < 32; i += 8) {
        float v = f[(size_t)(n0 + i) * DF + d0 + tx];
        t[i][tx] = v;
        g_cat[(size_t)(n0 + i) * KCAT + d0 + tx] = __float2half(v);
    }
    __syncthreads();
    #pragma unroll
    for (int i = ty; i < 32; i += 8)
        g_ftT[(size_t)(d0 + i) * NN + n0 + tx] = __float2half(t[tx][i]);
}

__global__ void __launch_bounds__(256) k_wconv(const float* __restrict__ W, int base) {
    int i = base + blockIdx.x * 256 + threadIdx.x;
    g_w[i] = __float2half(W[i]);
}

// ================= k_main: R8 mainloop + fused out-GEMM tail =================
__global__ void __launch_bounds__(512, 1) k_main(const float* __restrict__ adj,
                                                 float* __restrict__ out) {
    extern __shared__ char sm[];
    __half* Abuf  = (__half*)sm;                 // mainloop A [2][128][72]
    __half* Bbuf  = (__half*)(sm + OFF_BM);      // mainloop B [3][256][72]
    __half* Nbuf  = (__half*)sm;                 // tail: neigh [128][264]
    __half* AbufO = (__half*)(sm + OFF_AO);      // tail: A-out [4][128][40]
    __half* BbufO = (__half*)(sm + OFF_BO);      // tail: B-out [4][256][40]
    float*  srow  = (float*)(sm + OFF_SROW);     // [128]
    float*  stage = (float*)(sm + OFF_AO);       // f32 epilogue stage [128][68]

    const int tid = threadIdx.x;
    const int lane = tid & 31;
    const int wid = tid >> 5;
    const int wm = wid >> 2, wn = wid & 3;       // 4x4 warps, 32x64 tiles
    const int m0 = blockIdx.x * 128;
    const uint32_t b_u32 = smem_u32(Bbuf);
    const uint32_t ao_u32 = smem_u32(AbufO);
    const uint32_t bo_u32 = smem_u32(BbufO);

    float rowacc[4] = {0.f, 0.f, 0.f, 0.f};
    float4 va[4];

    auto ldgA = [&](int it) {
        int k0 = it * 64;
        #pragma unroll
        for (int j = 0; j < 4; j++) {
            int idx = tid + j * 512;
            int row = idx >> 4, c4 = idx & 15;
            va[j] = *(const float4*)(adj + (size_t)(m0 + row) * NN + k0 + c4 * 4);
        }
    };
    auto stsA = [&](int buf) {
        __half* At = Abuf + buf * 128 * ASTM;
        #pragma unroll
        for (int j = 0; j < 4; j++) {
            int idx = tid + j * 512;
            int row = idx >> 4, c4 = idx & 15;
            float4 v = va[j];
            rowacc[j] += (v.x + v.y) + (v.z + v.w);
            __half2 h0 = __floats2half2_rn(v.x, v.y);
            __half2 h1 = __floats2half2_rn(v.z, v.w);
            uint2 u;
            u.x = *(uint32_t*)&h0;
            u.y = *(uint32_t*)&h1;
            *(uint2*)(At + row * ASTM + c4 * 4) = u;
        }
    };
    auto cpaB = [&](int buf, int it) {
        int k0 = it * 64;
        uint32_t b0 = b_u32 + buf * B_STG;
        #pragma unroll
        for (int j = 0; j < 4; j++) {
            int idx = tid + j * 512;
            int row = idx >> 3, c16 = idx & 7;
            cpa16(b0 + (row * ASTM + c16 * 8) * 2, g_ftT + (size_t)row * NN + k0 + c16 * 8);
        }
    };

    // ================== mainloop (frozen R8) ==================
    {
        wmma::fragment<wmma::accumulator, 16, 16, 16, __half> acc[2][4];
        #pragma unroll
        for (int mi = 0; mi < 2; mi++)
            #pragma unroll
            for (int ni = 0; ni < 4; ni++)
                wmma::fill_fragment(acc[mi][ni], __float2half(0.0f));

        ldgA(0);
        stsA(0);
        ldgA(1);
        cpaB(0, 0); cpa_commit();
        cpaB(1, 1); cpa_commit();

        constexpr int NK = NN / 64;  // 256
        int bs = 0, bs2 = 2;

        #pragma unroll 1
        for (int it = 0; it < NK; ++it) {
            int cur = it & 1;
            cpa_wait1();
            __syncthreads();

            if (it + 1 < NK) stsA(cur ^ 1);
            if (it + 2 < NK) {
                ldgA(it + 2);
                cpaB(bs2, it + 2);
            }
            cpa_commit();

            const __half* At = Abuf + cur * 128 * ASTM;
            const __half* Bt = Bbuf + bs * 256 * ASTM;
            #pragma unroll
            for (int ks = 0; ks < 4; ++ks) {
                wmma::fragment<wmma::matrix_a, 16, 16, 16, __half, wmma::row_major> af[2];
                #pragma unroll
                for (int mi = 0; mi < 2; mi++)
                    wmma::load_matrix_sync(af[mi], At + (wm * 32 + mi * 16) * ASTM + ks * 16, ASTM);
                #pragma unroll
                for (int ni = 0; ni < 4; ni++) {
                    wmma::fragment<wmma::matrix_b, 16, 16, 16, __half, wmma::col_major> bf;
                    wmma::load_matrix_sync(bf, Bt + (wn * 64 + ni * 16) * ASTM + ks * 16, ASTM);
                    #pragma unroll
                    for (int mi = 0; mi < 2; mi++)
                        wmma::mma_sync(acc[mi][ni], af[mi], bf, acc[mi][ni]);
                }
            }
            bs = (bs == 2) ? 0 : bs + 1;
            bs2 = (bs2 == 2) ? 0 : bs2 + 1;
        }
        cpa_wait0();

        // exact fp32 rowsum -> 1/(deg+1)
        #pragma unroll
        for (int j = 0; j < 4; j++) {
            float s = rowacc[j];
            s += __shfl_xor_sync(0xFFFFFFFFu, s, 1);
            s += __shfl_xor_sync(0xFFFFFFFFu, s, 2);
            s += __shfl_xor_sync(0xFFFFFFFFu, s, 4);
            s += __shfl_xor_sync(0xFFFFFFFFu, s, 8);
            int row = (tid + j * 512) >> 4;
            if ((lane & 15) == 0) srow[row] = 1.0f / (s + 1.0f);
        }
        __syncthreads();  // mainloop smem reads done; srow visible; Nbuf region free

        // stage ALL fragments into Nbuf (raw P values)
        #pragma unroll
        for (int mi = 0; mi < 2; mi++)
            #pragma unroll
            for (int ni = 0; ni < 4; ni++)
                wmma::store_matrix_sync(Nbuf + (wm * 32 + mi * 16) * ASTN + wn * 64 + ni * 16,
                                        acc[mi][ni], ASTN, wmma::mem_row_major);
    }
    __syncthreads();

    // in-place scale: neigh = P * srow[r]   (128x256 halves = 16384 half2)
    #pragma unroll
    for (int j = 0; j < 32; j++) {
        int idx = tid + j * 512;
        int r = idx >> 7, c2 = idx & 127;
        __half2* p = (__half2*)(Nbuf + r * ASTN + c2 * 2);
        float iv = srow[r];
        __half2 v = *p;
        *p = __floats2half2_rn(__half2float(__low2half(v)) * iv,
                               __half2float(__high2half(v)) * iv);
    }
    __syncthreads();

    // ================== fused out-GEMM: out = [F|neigh] @ W^T, K=512 ==================
    {
        wmma::fragment<wmma::accumulator, 16, 16, 16, float> acc[2][4];
        #pragma unroll
        for (int mi = 0; mi < 2; mi++)
            #pragma unroll
            for (int ni = 0; ni < 4; ni++)
                wmma::fill_fragment(acc[mi][ni], 0.0f);

        auto loadTileO = [&](int slot, int it) {
            int k0 = it * 32;
            if (it < 8) {  // A from g_cat features half
                int row = tid >> 2, c8 = tid & 3;
                cpa16(ao_u32 + slot * AO_STG + (row * AST + c8 * 8) * 2,
                      g_cat + (size_t)(m0 + row) * KCAT + k0 + c8 * 8);
            }
            #pragma unroll
            for (int j = 0; j < 2; j++) {  // B from g_w
                int idx = tid + j * 512;
                int row = idx >> 2, c8 = idx & 3;
                cpa16(bo_u32 + slot * BO_STG + (row * AST + c8 * 8) * 2,
                      g_w + (size_t)row * KCAT + k0 + c8 * 8);
            }
        };

        loadTileO(0, 0); cpa_commit();
        loadTileO(1, 1); cpa_commit();
        loadTileO(2, 2); cpa_commit();

        constexpr int NKO = KCAT / 32;  // 16
        #pragma unroll 1
        for (int it = 0; it < NKO; ++it) {
            cpa_wait2();
            __syncthreads();

            if (it + 3 < NKO) { loadTileO((it + 3) & 3, it + 3); cpa_commit(); }

            const __half* At;
            int lda;
            if (it < 8) { At = AbufO + (it & 3) * 128 * AST; lda = AST; }
            else        { At = Nbuf + (it - 8) * 32;         lda = ASTN; }
            const __half* Bt = BbufO + (it & 3) * 256 * AST;
            #pragma unroll
            for (int ks = 0; ks < 2; ++ks) {
                wmma::fragment<wmma::matrix_a, 16, 16, 16, __half, wmma::row_major> af[2];
                #pragma unroll
                for (int mi = 0; mi < 2; mi++)
                    wmma::load_matrix_sync(af[mi], At + (wm * 32 + mi * 16) * lda + ks * 16, lda);
                #pragma unroll
                for (int ni = 0; ni < 4; ni++) {
                    wmma::fragment<wmma::matrix_b, 16, 16, 16, __half, wmma::col_major> bf;
                    wmma::load_matrix_sync(bf, Bt + (wn * 64 + ni * 16) * AST + ks * 16, AST);
                    #pragma unroll
                    for (int mi = 0; mi < 2; mi++)
                        wmma::mma_sync(acc[mi][ni], af[mi], bf, acc[mi][ni]);
                }
            }
        }
        cpa_wait0();
        __syncthreads();  // safe to overwrite AbufO with f32 stage

        #pragma unroll 1
        for (int p = 0; p < 4; p++) {
            if (wn == p) {
                #pragma unroll
                for (int mi = 0; mi < 2; mi++)
                    #pragma unroll
                    for (int ni = 0; ni < 4; ni++)
                        wmma::store_matrix_sync(stage + (wm * 32 + mi * 16) * SST + ni * 16,
                                                acc[mi][ni], SST, wmma::mem_row_major);
            }
            __syncthreads();
            #pragma unroll
            for (int j = 0; j < 16; j++) {
                int idx = tid + j * 512;
                int r = idx >> 6, c = idx & 63;
                out[(size_t)(m0 + r) * DF + p * 64 + c] = stage[r * SST + c];
            }
            __syncthreads();
        }
    }
}

// ---------------- launch ----------------
extern "C" void kernel_launch(void* const* d_in, const int* in_sizes, int n_in,
                              void* d_out, int out_size) {
    const float* features = nullptr;
    const float* adj = nullptr;
    const float* W = nullptr;
    for (int i = 0; i < n_in; i++) {
        if (in_sizes[i] == NN * NN) adj = (const float*)d_in[i];
        else if (in_sizes[i] == NN * DF) features = (const float*)d_in[i];
        else if (in_sizes[i] == DF * KCAT) W = (const float*)d_in[i];
    }
    float* out = (float*)d_out;

    cudaFuncSetAttribute(k_main, cudaFuncAttributeMaxDynamicSharedMemorySize, SMEM_MAIN);

    // k_main stays at launch index 3 (ncu capture slot)
    k_prep<<<dim3(NN / 32, DF / 32), dim3(32, 8)>>>(features);
    k_wconv<<<(DF * KCAT / 2) / 256, 256>>>(W, 0);
    k_wconv<<<(DF * KCAT / 2) / 256, 256>>>(W, DF * KCAT / 2);
    k_main<<<NN / 128, 512, SMEM_MAIN>>>(adj, out);
}

// round 13
// speedup vs baseline: 1.2886x; 1.0061x over previous
#include <cuda_runtime.h>
#include <cuda_fp16.h>
#include <mma.h>
#include <cstdint>
#include <cstddef>

using namespace nvcuda;

#define NN   16384
#define DF   256
#define KCAT 512

// ---------------- device-global scratch ----------------
__device__ __half g_ftT[(size_t)DF * NN];    // features^T fp16 [256][16384]
__device__ __half g_cat[(size_t)NN * KCAT];  // [features | neigh] fp16 [16384][512]
__device__ __half g_w[(size_t)DF * KCAT];    // W fp16 [256][512]

// ---------------- k_main smem (frozen R8) ----------------
constexpr int ASTM = 72;
constexpr int A_STG = 128 * ASTM * 2;         // 18432
constexpr int B_STG = 256 * ASTM * 2;         // 36864
constexpr int OFF_BM = 2 * A_STG;             // 36864
constexpr int OFF_SROW = OFF_BM + 3 * B_STG;  // 147456
constexpr int SMEM_MAIN = OFF_SROW + 512;

// ---------------- k_out smem: BM=64, 4-stage, 2 CTAs/SM ----------------
constexpr int AST = 40;                        // row stride (halves)
constexpr int AO_STG = 64 * AST * 2;           // 5120 B
constexpr int BO_STG = 256 * AST * 2;          // 20480 B
constexpr int OFF_BO = 4 * AO_STG;             // 20480
constexpr int SST = 68;                        // f32 stage stride (reuses A region: 64*68*4=17408 <= 20480)
constexpr int SMEM_OUT = OFF_BO + 4 * BO_STG;  // 102400  (x2 CTAs = 204800 < 228KB)

__device__ __forceinline__ uint32_t smem_u32(const void* p) {
    uint32_t a;
    asm("{ .reg .u64 t; cvta.to.shared.u64 t, %1; cvt.u32.u64 %0, t; }" : "=r"(a) : "l"(p));
    return a;
}
__device__ __forceinline__ void cpa16(uint32_t saddr, const void* g) {
    asm volatile("cp.async.cg.shared.global [%0], [%1], 16;" :: "r"(saddr), "l"(g));
}
__device__ __forceinline__ void cpa_commit() { asm volatile("cp.async.commit_group;" ::: "memory"); }
__device__ __forceinline__ void cpa_wait0()  { asm volatile("cp.async.wait_group 0;" ::: "memory"); }
__device__ __forceinline__ void cpa_wait1()  { asm volatile("cp.async.wait_group 1;" ::: "memory"); }
__device__ __forceinline__ void cpa_wait2()  { asm volatile("cp.async.wait_group 2;" ::: "memory"); }

// ---------------- prep ----------------
__global__ void __launch_bounds__(256) k_prep(const float* __restrict__ f) {
    __shared__ float t[32][33];
    int n0 = blockIdx.x * 32, d0 = blockIdx.y * 32;
    int tx = threadIdx.x, ty = threadIdx.y;
    #pragma unroll
    for (int i = ty; i < 32; i += 8) {
        float v = f[(size_t)(n0 + i) * DF + d0 + tx];
        t[i][tx] = v;
        g_cat[(size_t)(n0 + i) * KCAT + d0 + tx] = __float2half(v);
    }
    __syncthreads();
    #pragma unroll
    for (int i = ty; i < 32; i += 8)
        g_ftT[(size_t)(d0 + i) * NN + n0 + tx] = __float2half(t[tx][i]);
}

__global__ void __launch_bounds__(256) k_wconv(const float* __restrict__ W, int base) {
    int i = base + blockIdx.x * 256 + threadIdx.x;
    g_w[i] = __float2half(W[i]);
}

// ================= k_main: FROZEN R8 (512 threads, BM=128, 16 warps, 32x64 tiles) =================
__global__ void __launch_bounds__(512, 1) k_main(const float* __restrict__ adj) {
    extern __shared__ char sm[];
    __half* Abuf = (__half*)sm;
    __half* Bbuf = (__half*)(sm + OFF_BM);
    float*  srow = (float*)(sm + OFF_SROW);
    __half* hstage = (__half*)sm;

    const int tid = threadIdx.x;
    const int lane = tid & 31;
    const int wid = tid >> 5;
    const int wm = wid >> 2, wn = wid & 3;
    const int m0 = blockIdx.x * 128;
    const uint32_t b_u32 = smem_u32(Bbuf);

    wmma::fragment<wmma::accumulator, 16, 16, 16, __half> acc[2][4];
    #pragma unroll
    for (int mi = 0; mi < 2; mi++)
        #pragma unroll
        for (int ni = 0; ni < 4; ni++)
            wmma::fill_fragment(acc[mi][ni], __float2half(0.0f));

    float rowacc[4] = {0.f, 0.f, 0.f, 0.f};
    float4 va[4];

    auto ldgA = [&](int it) {
        int k0 = it * 64;
        #pragma unroll
        for (int j = 0; j < 4; j++) {
            int idx = tid + j * 512;
            int row = idx >> 4, c4 = idx & 15;
            va[j] = *(const float4*)(adj + (size_t)(m0 + row) * NN + k0 + c4 * 4);
        }
    };
    auto stsA = [&](int buf) {
        __half* At = Abuf + buf * 128 * ASTM;
        #pragma unroll
        for (int j = 0; j < 4; j++) {
            int idx = tid + j * 512;
            int row = idx >> 4, c4 = idx & 15;
            float4 v = va[j];
            rowacc[j] += (v.x + v.y) + (v.z + v.w);
            __half2 h0 = __floats2half2_rn(v.x, v.y);
            __half2 h1 = __floats2half2_rn(v.z, v.w);
            uint2 u;
            u.x = *(uint32_t*)&h0;
            u.y = *(uint32_t*)&h1;
            *(uint2*)(At + row * ASTM + c4 * 4) = u;
        }
    };
    auto cpaB = [&](int buf, int it) {
        int k0 = it * 64;
        uint32_t b0 = b_u32 + buf * B_STG;
        #pragma unroll
        for (int j = 0; j < 4; j++) {
            int idx = tid + j * 512;
            int row = idx >> 3, c16 = idx & 7;
            cpa16(b0 + (row * ASTM + c16 * 8) * 2, g_ftT + (size_t)row * NN + k0 + c16 * 8);
        }
    };

    ldgA(0);
    stsA(0);
    ldgA(1);
    cpaB(0, 0); cpa_commit();
    cpaB(1, 1); cpa_commit();

    constexpr int NK = NN / 64;  // 256
    int bs = 0, bs2 = 2;

    #pragma unroll 1
    for (int it = 0; it < NK; ++it) {
        int cur = it & 1;
        cpa_wait1();
        __syncthreads();

        if (it + 1 < NK) stsA(cur ^ 1);
        if (it + 2 < NK) {
            ldgA(it + 2);
            cpaB(bs2, it + 2);
        }
        cpa_commit();

        const __half* At = Abuf + cur * 128 * ASTM;
        const __half* Bt = Bbuf + bs * 256 * ASTM;
        #pragma unroll
        for (int ks = 0; ks < 4; ++ks) {
            wmma::fragment<wmma::matrix_a, 16, 16, 16, __half, wmma::row_major> af[2];
            #pragma unroll
            for (int mi = 0; mi < 2; mi++)
                wmma::load_matrix_sync(af[mi], At + (wm * 32 + mi * 16) * ASTM + ks * 16, ASTM);
            #pragma unroll
            for (int ni = 0; ni < 4; ni++) {
                wmma::fragment<wmma::matrix_b, 16, 16, 16, __half, wmma::col_major> bf;
                wmma::load_matrix_sync(bf, Bt + (wn * 64 + ni * 16) * ASTM + ks * 16, ASTM);
                #pragma unroll
                for (int mi = 0; mi < 2; mi++)
                    wmma::mma_sync(acc[mi][ni], af[mi], bf, acc[mi][ni]);
            }
        }
        bs = (bs == 2) ? 0 : bs + 1;
        bs2 = (bs2 == 2) ? 0 : bs2 + 1;
    }
    cpa_wait0();

    #pragma unroll
    for (int j = 0; j < 4; j++) {
        float s = rowacc[j];
        s += __shfl_xor_sync(0xFFFFFFFFu, s, 1);
        s += __shfl_xor_sync(0xFFFFFFFFu, s, 2);
        s += __shfl_xor_sync(0xFFFFFFFFu, s, 4);
        s += __shfl_xor_sync(0xFFFFFFFFu, s, 8);
        int row = (tid + j * 512) >> 4;
        if ((lane & 15) == 0) srow[row] = 1.0f / (s + 1.0f);
    }
    __syncthreads();

    #pragma unroll 1
    for (int p = 0; p < 4; p++) {
        if (wn == p) {
            #pragma unroll
            for (int mi = 0; mi < 2; mi++)
                #pragma unroll
                for (int ni = 0; ni < 4; ni++)
                    wmma::store_matrix_sync(hstage + (wm * 32 + mi * 16) * ASTM + ni * 16,
                                            acc[mi][ni], ASTM, wmma::mem_row_major);
        }
        __syncthreads();
        #pragma unroll
        for (int j = 0; j < 16; j++) {
            int idx = tid + j * 512;
            int r = idx >> 6, c = idx & 63;
            float v = __half2float(hstage[r * ASTM + c]) * srow[r];
            g_cat[(size_t)(m0 + r) * KCAT + 256 + p * 64 + c] = __float2half(v);
        }
        __syncthreads();
    }
}

// ================= k_out: BM=64, 256 threads, 2 CTAs/SM, 4-stage depth-3 =================
__global__ void __launch_bounds__(256, 2) k_out(float* __restrict__ out) {
    extern __shared__ char sm[];
    __half* Abuf = (__half*)sm;                // [4][64][40]
    __half* Bbuf = (__half*)(sm + OFF_BO);     // [4][256][40]
    float*  stage = (float*)sm;                // epilogue reuse [64][68] f32

    const int tid = threadIdx.x;
    const int wid = tid >> 5;
    const int wm = wid >> 2, wn = wid & 3;     // 2x4 warps, 32x64 tiles over 64x256
    const int m0 = blockIdx.x * 64;
    const uint32_t a_u32 = smem_u32(Abuf);
    const uint32_t b_u32 = smem_u32(Bbuf);

    wmma::fragment<wmma::accumulator, 16, 16, 16, float> acc[2][4];
    #pragma unroll
    for (int mi = 0; mi < 2; mi++)
        #pragma unroll
        for (int ni = 0; ni < 4; ni++)
            wmma::fill_fragment(acc[mi][ni], 0.0f);

    auto loadTile = [&](int slot, int it) {
        int k0 = it * 32;
        uint32_t a0 = a_u32 + slot * AO_STG;
        uint32_t b0 = b_u32 + slot * BO_STG;
        {   // A: 64 rows x 4 x 16B = 256 chunks = 1/thread
            int row = tid >> 2, c8 = tid & 3;
            cpa16(a0 + (row * AST + c8 * 8) * 2, g_cat + (size_t)(m0 + row) * KCAT + k0 + c8 * 8);
        }
        #pragma unroll
        for (int j = 0; j < 4; j++) {  // B: 256 rows x 4 chunks = 1024 = 4/thread
            int idx = tid + j * 256;
            int row = idx >> 2, c8 = idx & 3;
            cpa16(b0 + (row * AST + c8 * 8) * 2, g_w + (size_t)row * KCAT + k0 + c8 * 8);
        }
    };

    loadTile(0, 0); cpa_commit();
    loadTile(1, 1); cpa_commit();
    loadTile(2, 2); cpa_commit();

    constexpr int NK = KCAT / 32;  // 16
    #pragma unroll 1
    for (int it = 0; it < NK; ++it) {
        int cur = it & 3;
        cpa_wait2();       // tile(it) landed
        __syncthreads();   // all warps done reading slot (it+3)%4

        if (it + 3 < NK) { loadTile((it + 3) & 3, it + 3); cpa_commit(); }

        const __half* At = Abuf + cur * 64 * AST;
        const __half* Bt = Bbuf + cur * 256 * AST;
        #pragma unroll
        for (int ks = 0; ks < 2; ++ks) {
            wmma::fragment<wmma::matrix_a, 16, 16, 16, __half, wmma::row_major> af[2];
            #pragma unroll
            for (int mi = 0; mi < 2; mi++)
                wmma::load_matrix_sync(af[mi], At + (wm * 32 + mi * 16) * AST + ks * 16, AST);
            #pragma unroll
            for (int ni = 0; ni < 4; ni++) {
                wmma::fragment<wmma::matrix_b, 16, 16, 16, __half, wmma::col_major> bf;
                wmma::load_matrix_sync(bf, Bt + (wn * 64 + ni * 16) * AST + ks * 16, AST);
                #pragma unroll
                for (int mi = 0; mi < 2; mi++)
                    wmma::mma_sync(acc[mi][ni], af[mi], bf, acc[mi][ni]);
            }
        }
    }
    cpa_wait0();
    __syncthreads();  // safe to overwrite Abuf with f32 stage

    #pragma unroll 1
    for (int p = 0; p < 4; p++) {
        if (wn == p) {
            #pragma unroll
            for (int mi = 0; mi < 2; mi++)
                #pragma unroll
                for (int ni = 0; ni < 4; ni++)
                    wmma::store_matrix_sync(stage + (wm * 32 + mi * 16) * SST + ni * 16,
                                            acc[mi][ni], SST, wmma::mem_row_major);
        }
        __syncthreads();
        #pragma unroll
        for (int j = 0; j < 16; j++) {   // 64*64 = 4096 = 256*16
            int idx = tid + j * 256;
            int r = idx >> 6, c = idx & 63;
            out[(size_t)(m0 + r) * DF + p * 64 + c] = stage[r * SST + c];
        }
        __syncthreads();
    }
}

// ---------------- launch ----------------
extern "C" void kernel_launch(void* const* d_in, const int* in_sizes, int n_in,
                              void* d_out, int out_size) {
    const float* features = nullptr;
    const float* adj = nullptr;
    const float* W = nullptr;
    for (int i = 0; i < n_in; i++) {
        if (in_sizes[i] == NN * NN) adj = (const float*)d_in[i];
        else if (in_sizes[i] == NN * DF) features = (const float*)d_in[i];
        else if (in_sizes[i] == DF * KCAT) W = (const float*)d_in[i];
    }
    float* out = (float*)d_out;

    cudaFuncSetAttribute(k_main, cudaFuncAttributeMaxDynamicSharedMemorySize, SMEM_MAIN);
    cudaFuncSetAttribute(k_out,  cudaFuncAttributeMaxDynamicSharedMemorySize, SMEM_OUT);

    // k_main stays at launch index 3 (ncu capture slot)
    k_prep<<<dim3(NN / 32, DF / 32), dim3(32, 8)>>>(features);
    k_wconv<<<(DF * KCAT / 2) / 256, 256>>>(W, 0);
    k_wconv<<<(DF * KCAT / 2) / 256, 256>>>(W, DF * KCAT / 2);
    k_main<<<NN / 128, 512, SMEM_MAIN>>>(adj);
    k_out<<<NN / 64, 256, SMEM_OUT>>>(out);
}

// round 15
// speedup vs baseline: 1.3085x; 1.0154x over previous
#include <cuda_runtime.h>
#include <cuda_fp16.h>
#include <mma.h>
#include <cstdint>
#include <cstddef>

using namespace nvcuda;

#define NN   16384
#define DF   256
#define KCAT 512
#define NSLC 8            // split-K slices
#define SLC_ITERS 32      // 256/8 K-iters (of 64) per slice

// ---------------- device-global scratch ----------------
__device__ __half g_ftT[(size_t)DF * NN];        // features^T fp16 [256][16384]
__device__ __half g_cat[(size_t)NN * KCAT];      // [features | neigh] fp16
__device__ __half g_w[(size_t)DF * KCAT];        // W fp16 [256][512]
__device__ __half g_part[(size_t)NSLC * NN * DF];// P partials fp16 [8][16384][256] = 67MB
__device__ float  g_rs[(size_t)NSLC * NN];       // rowsum partials
__device__ float  g_srow[NN];                    // 1/(deg+1)

// ---------------- k_main smem (mainloop regions frozen from R8) ----------------
constexpr int ASTM = 72;
constexpr int A_STG = 128 * ASTM * 2;         // 18432
constexpr int B_STG = 256 * ASTM * 2;         // 36864
constexpr int OFF_BM = 2 * A_STG;             // 36864
constexpr int SMEM_MAIN = OFF_BM + 3 * B_STG; // 147456

// ---------------- k_out smem: BM=64, 4-stage, 2 CTAs/SM (frozen R13) ----------------
constexpr int AST = 40;
constexpr int AO_STG = 64 * AST * 2;           // 5120
constexpr int BO_STG = 256 * AST * 2;          // 20480
constexpr int OFF_BO = 4 * AO_STG;             // 20480
constexpr int SST = 68;
constexpr int SMEM_OUT = OFF_BO + 4 * BO_STG;  // 102400

__device__ __forceinline__ uint32_t smem_u32(const void* p) {
    uint32_t a;
    asm("{ .reg .u64 t; cvta.to.shared.u64 t, %1; cvt.u32.u64 %0, t; }" : "=r"(a) : "l"(p));
    return a;
}
__device__ __forceinline__ void cpa16(uint32_t saddr, const void* g) {
    asm volatile("cp.async.cg.shared.global [%0], [%1], 16;" :: "r"(saddr), "l"(g));
}
__device__ __forceinline__ void cpa_commit() { asm volatile("cp.async.commit_group;" ::: "memory"); }
__device__ __forceinline__ void cpa_wait0()  { asm volatile("cp.async.wait_group 0;" ::: "memory"); }
__device__ __forceinline__ void cpa_wait1()  { asm volatile("cp.async.wait_group 1;" ::: "memory"); }
__device__ __forceinline__ void cpa_wait2()  { asm volatile("cp.async.wait_group 2;" ::: "memory"); }

// ---------------- prep ----------------
__global__ void __launch_bounds__(256) k_prep(const float* __restrict__ f) {
    __shared__ float t[32][33];
    int n0 = blockIdx.x * 32, d0 = blockIdx.y * 32;
    int tx = threadIdx.x, ty = threadIdx.y;
    #pragma unroll
    for (int i = ty; i < 32; i += 8) {
        float v = f[(size_t)(n0 + i) * DF + d0 + tx];
        t[i][tx] = v;
        g_cat[(size_t)(n0 + i) * KCAT + d0 + tx] = __float2half(v);
    }
    __syncthreads();
    #pragma unroll
    for (int i = ty; i < 32; i += 8)
        g_ftT[(size_t)(d0 + i) * NN + n0 + tx] = __float2half(t[tx][i]);
}

__global__ void __launch_bounds__(256) k_wconv(const float* __restrict__ W, int base) {
    int i = base + blockIdx.x * 256 + threadIdx.x;
    g_w[i] = __float2half(W[i]);
}

// ================= k_main: split-K slice GEMM (R8 mainloop, 32 iters/slice) =================
__global__ void __launch_bounds__(512, 1) k_main(const float* __restrict__ adj) {
    extern __shared__ char sm[];
    __half* Abuf = (__half*)sm;                // [2][128][72]
    __half* Bbuf = (__half*)(sm + OFF_BM);     // [3][256][72]

    const int tid = threadIdx.x;
    const int lane = tid & 31;
    const int wid = tid >> 5;
    const int wm = wid >> 2, wn = wid & 3;     // 4x4 warps, 32x64 tiles
    const int m0 = blockIdx.x * 128;
    const int slc = blockIdx.y;                // 0..7
    const int K0 = slc * SLC_ITERS;            // global 64-iter base
    const uint32_t b_u32 = smem_u32(Bbuf);

    wmma::fragment<wmma::accumulator, 16, 16, 16, __half> acc[2][4];
    #pragma unroll
    for (int mi = 0; mi < 2; mi++)
        #pragma unroll
        for (int ni = 0; ni < 4; ni++)
            wmma::fill_fragment(acc[mi][ni], __float2half(0.0f));

    float rowacc[4] = {0.f, 0.f, 0.f, 0.f};
    float4 va[4];

    auto ldgA = [&](int it) {                  // it = slice-local
        int k0 = (K0 + it) * 64;
        #pragma unroll
        for (int j = 0; j < 4; j++) {
            int idx = tid + j * 512;
            int row = idx >> 4, c4 = idx & 15;
            va[j] = *(const float4*)(adj + (size_t)(m0 + row) * NN + k0 + c4 * 4);
        }
    };
    auto stsA = [&](int buf) {
        __half* At = Abuf + buf * 128 * ASTM;
        #pragma unroll
        for (int j = 0; j < 4; j++) {
            int idx = tid + j * 512;
            int row = idx >> 4, c4 = idx & 15;
            float4 v = va[j];
            rowacc[j] += (v.x + v.y) + (v.z + v.w);
            __half2 h0 = __floats2half2_rn(v.x, v.y);
            __half2 h1 = __floats2half2_rn(v.z, v.w);
            uint2 u;
            u.x = *(uint32_t*)&h0;
            u.y = *(uint32_t*)&h1;
            *(uint2*)(At + row * ASTM + c4 * 4) = u;
        }
    };
    auto cpaB = [&](int buf, int it) {
        int k0 = (K0 + it) * 64;
        uint32_t b0 = b_u32 + buf * B_STG;
        #pragma unroll
        for (int j = 0; j < 4; j++) {
            int idx = tid + j * 512;
            int row = idx >> 3, c16 = idx & 7;
            cpa16(b0 + (row * ASTM + c16 * 8) * 2, g_ftT + (size_t)row * NN + k0 + c16 * 8);
        }
    };

    ldgA(0);
    stsA(0);
    ldgA(1);
    cpaB(0, 0); cpa_commit();
    cpaB(1, 1); cpa_commit();

    constexpr int NK = SLC_ITERS;  // 32
    int bs = 0, bs2 = 2;

    #pragma unroll 1
    for (int it = 0; it < NK; ++it) {
        int cur = it & 1;
        cpa_wait1();
        __syncthreads();

        if (it + 1 < NK) stsA(cur ^ 1);
        if (it + 2 < NK) {
            ldgA(it + 2);
            cpaB(bs2, it + 2);
        }
        cpa_commit();

        const __half* At = Abuf + cur * 128 * ASTM;
        const __half* Bt = Bbuf + bs * 256 * ASTM;
        #pragma unroll
        for (int ks = 0; ks < 4; ++ks) {
            wmma::fragment<wmma::matrix_a, 16, 16, 16, __half, wmma::row_major> af[2];
            #pragma unroll
            for (int mi = 0; mi < 2; mi++)
                wmma::load_matrix_sync(af[mi], At + (wm * 32 + mi * 16) * ASTM + ks * 16, ASTM);
            #pragma unroll
            for (int ni = 0; ni < 4; ni++) {
                wmma::fragment<wmma::matrix_b, 16, 16, 16, __half, wmma::col_major> bf;
                wmma::load_matrix_sync(bf, Bt + (wn * 64 + ni * 16) * ASTM + ks * 16, ASTM);
                #pragma unroll
                for (int mi = 0; mi < 2; mi++)
                    wmma::mma_sync(acc[mi][ni], af[mi], bf, acc[mi][ni]);
            }
        }
        bs = (bs == 2) ? 0 : bs + 1;
        bs2 = (bs2 == 2) ? 0 : bs2 + 1;
    }
    cpa_wait0();

    // partial rowsum -> g_rs (raw sum; combined later)
    #pragma unroll
    for (int j = 0; j < 4; j++) {
        float s = rowacc[j];
        s += __shfl_xor_sync(0xFFFFFFFFu, s, 1);
        s += __shfl_xor_sync(0xFFFFFFFFu, s, 2);
        s += __shfl_xor_sync(0xFFFFFFFFu, s, 4);
        s += __shfl_xor_sync(0xFFFFFFFFu, s, 8);
        int row = (tid + j * 512) >> 4;
        if ((lane & 15) == 0) g_rs[(size_t)slc * NN + m0 + row] = s;
    }

    // partial P -> g_part fp16, direct fragment stores (no smem staging)
    __half* dst = g_part + ((size_t)slc * NN + m0) * DF;
    #pragma unroll
    for (int mi = 0; mi < 2; mi++)
        #pragma unroll
        for (int ni = 0; ni < 4; ni++)
            wmma::store_matrix_sync(dst + (wm * 32 + mi * 16) * DF + wn * 64 + ni * 16,
                                    acc[mi][ni], DF, wmma::mem_row_major);
}

// ================= combine: srow, then neigh = sum(P_s)*srow -> g_cat =================
__global__ void __launch_bounds__(256) k_srow() {
    int i = blockIdx.x * 256 + threadIdx.x;
    float s = 0.f;
    #pragma unroll
    for (int t = 0; t < NSLC; t++) s += g_rs[(size_t)t * NN + i];
    g_srow[i] = 1.0f / (s + 1.0f);
}

__global__ void __launch_bounds__(256) k_reduce() {
    int idx = blockIdx.x * 256 + threadIdx.x;      // 16384*64 groups of 4 cols
    int row = idx >> 6, g = idx & 63;
    float s0 = 0.f, s1 = 0.f, s2 = 0.f, s3 = 0.f;
    #pragma unroll
    for (int t = 0; t < NSLC; t++) {
        uint2 u = *(const uint2*)(g_part + ((size_t)t * NN + row) * DF + g * 4);
        __half2 a = *(__half2*)&u.x, b = *(__half2*)&u.y;
        s0 += __half2float(__low2half(a));
        s1 += __half2float(__high2half(a));
        s2 += __half2float(__low2half(b));
        s3 += __half2float(__high2half(b));
    }
    float iv = g_srow[row];
    __half2 h0 = __floats2half2_rn(s0 * iv, s1 * iv);
    __half2 h1 = __floats2half2_rn(s2 * iv, s3 * iv);
    uint2 o;
    o.x = *(uint32_t*)&h0;
    o.y = *(uint32_t*)&h1;
    *(uint2*)(g_cat + (size_t)row * KCAT + 256 + g * 4) = o;
}

// ================= k_out: BM=64, 256 threads, 2 CTAs/SM (frozen R13) =================
__global__ void __launch_bounds__(256, 2) k_out(float* __restrict__ out) {
    extern __shared__ char sm[];
    __half* Abuf = (__half*)sm;                // [4][64][40]
    __half* Bbuf = (__half*)(sm + OFF_BO);     // [4][256][40]
    float*  stage = (float*)sm;                // epilogue reuse [64][68]

    const int tid = threadIdx.x;
    const int wid = tid >> 5;
    const int wm = wid >> 2, wn = wid & 3;
    const int m0 = blockIdx.x * 64;
    const uint32_t a_u32 = smem_u32(Abuf);
    const uint32_t b_u32 = smem_u32(Bbuf);

    wmma::fragment<wmma::accumulator, 16, 16, 16, float> acc[2][4];
    #pragma unroll
    for (int mi = 0; mi < 2; mi++)
        #pragma unroll
        for (int ni = 0; ni < 4; ni++)
            wmma::fill_fragment(acc[mi][ni], 0.0f);

    auto loadTile = [&](int slot, int it) {
        int k0 = it * 32;
        uint32_t a0 = a_u32 + slot * AO_STG;
        uint32_t b0 = b_u32 + slot * BO_STG;
        {
            int row = tid >> 2, c8 = tid & 3;
            cpa16(a0 + (row * AST + c8 * 8) * 2, g_cat + (size_t)(m0 + row) * KCAT + k0 + c8 * 8);
        }
        #pragma unroll
        for (int j = 0; j < 4; j++) {
            int idx = tid + j * 256;
            int row = idx >> 2, c8 = idx & 3;
            cpa16(b0 + (row * AST + c8 * 8) * 2, g_w + (size_t)row * KCAT + k0 + c8 * 8);
        }
    };

    loadTile(0, 0); cpa_commit();
    loadTile(1, 1); cpa_commit();
    loadTile(2, 2); cpa_commit();

    constexpr int NK = KCAT / 32;  // 16
    #pragma unroll 1
    for (int it = 0; it < NK; ++it) {
        int cur = it & 3;
        cpa_wait2();
        __syncthreads();

        if (it + 3 < NK) { loadTile((it + 3) & 3, it + 3); cpa_commit(); }

        const __half* At = Abuf + cur * 64 * AST;
        const __half* Bt = Bbuf + cur * 256 * AST;
        #pragma unroll
        for (int ks = 0; ks < 2; ++ks) {
            wmma::fragment<wmma::matrix_a, 16, 16, 16, __half, wmma::row_major> af[2];
            #pragma unroll
            for (int mi = 0; mi < 2; mi++)
                wmma::load_matrix_sync(af[mi], At + (wm * 32 + mi * 16) * AST + ks * 16, AST);
            #pragma unroll
            for (int ni = 0; ni < 4; ni++) {
                wmma::fragment<wmma::matrix_b, 16, 16, 16, __half, wmma::col_major> bf;
                wmma::load_matrix_sync(bf, Bt + (wn * 64 + ni * 16) * AST + ks * 16, AST);
                #pragma unroll
                for (int mi = 0; mi < 2; mi++)
                    wmma::mma_sync(acc[mi][ni], af[mi], bf, acc[mi][ni]);
            }
        }
    }
    cpa_wait0();
    __syncthreads();

    #pragma unroll 1
    for (int p = 0; p < 4; p++) {
        if (wn == p) {
            #pragma unroll
            for (int mi = 0; mi < 2; mi++)
                #pragma unroll
                for (int ni = 0; ni < 4; ni++)
                    wmma::store_matrix_sync(stage + (wm * 32 + mi * 16) * SST + ni * 16,
                                            acc[mi][ni], SST, wmma::mem_row_major);
        }
        __syncthreads();
        #pragma unroll
        for (int j = 0; j < 16; j++) {
            int idx = tid + j * 256;
            int r = idx >> 6, c = idx & 63;
            out[(size_t)(m0 + r) * DF + p * 64 + c] = stage[r * SST + c];
        }
        __syncthreads();
    }
}

// ---------------- launch ----------------
extern "C" void kernel_launch(void* const* d_in, const int* in_sizes, int n_in,
                              void* d_out, int out_size) {
    const float* features = nullptr;
    const float* adj = nullptr;
    const float* W = nullptr;
    for (int i = 0; i < n_in; i++) {
        if (in_sizes[i] == NN * NN) adj = (const float*)d_in[i];
        else if (in_sizes[i] == NN * DF) features = (const float*)d_in[i];
        else if (in_sizes[i] == DF * KCAT) W = (const float*)d_in[i];
    }
    float* out = (float*)d_out;

    cudaFuncSetAttribute(k_main, cudaFuncAttributeMaxDynamicSharedMemorySize, SMEM_MAIN);
    cudaFuncSetAttribute(k_out,  cudaFuncAttributeMaxDynamicSharedMemorySize, SMEM_OUT);

    // k_main at launch index 3 (ncu capture slot)
    k_prep<<<dim3(NN / 32, DF / 32), dim3(32, 8)>>>(features);
    k_wconv<<<(DF * KCAT / 2) / 256, 256>>>(W, 0);
    k_wconv<<<(DF * KCAT / 2) / 256, 256>>>(W, DF * KCAT / 2);
    k_main<<<dim3(NN / 128, NSLC), 512, SMEM_MAIN>>>(adj);
    k_srow<<<NN / 256, 256>>>();
    k_reduce<<<NN * 64 / 256, 256>>>();
    k_out<<<NN / 64, 256, SMEM_OUT>>>(out);
}

// round 16
// speedup vs baseline: 1.3129x; 1.0034x over previous
#include <cuda_runtime.h>
#include <cuda_fp16.h>
#include <mma.h>
#include <cstdint>
#include <cstddef>

using namespace nvcuda;

#define NN   16384
#define DF   256
#define KCAT 512
#define NSLC 8            // split-K slices
#define SLC_ITERS 32      // 256/8 K-iters (of 64) per slice

// ---------------- device-global scratch ----------------
__device__ __half g_ftT[(size_t)DF * NN];        // features^T fp16 [256][16384]
__device__ __half g_cat[(size_t)NN * KCAT];      // [features | neigh] fp16
__device__ __half g_w[(size_t)DF * KCAT];        // W fp16 [256][512]
__device__ __half g_part[(size_t)NSLC * NN * DF];// P partials fp16 [8][16384][256]
__device__ float  g_rs[(size_t)NSLC * NN];       // rowsum partials

// ---------------- k_main smem (frozen R8/R15) ----------------
constexpr int ASTM = 72;
constexpr int A_STG = 128 * ASTM * 2;         // 18432
constexpr int B_STG = 256 * ASTM * 2;         // 36864
constexpr int OFF_BM = 2 * A_STG;             // 36864
constexpr int SMEM_MAIN = OFF_BM + 3 * B_STG; // 147456

// ---------------- k_out smem: BM=64, 4-stage, 2 CTAs/SM (frozen R13) ----------------
constexpr int AST = 40;
constexpr int AO_STG = 64 * AST * 2;           // 5120
constexpr int BO_STG = 256 * AST * 2;          // 20480
constexpr int OFF_BO = 4 * AO_STG;             // 20480
constexpr int SST = 68;
constexpr int SMEM_OUT = OFF_BO + 4 * BO_STG;  // 102400

__device__ __forceinline__ uint32_t smem_u32(const void* p) {
    uint32_t a;
    asm("{ .reg .u64 t; cvta.to.shared.u64 t, %1; cvt.u32.u64 %0, t; }" : "=r"(a) : "l"(p));
    return a;
}
__device__ __forceinline__ void cpa16(uint32_t saddr, const void* g) {
    asm volatile("cp.async.cg.shared.global [%0], [%1], 16;" :: "r"(saddr), "l"(g));
}
__device__ __forceinline__ void cpa_commit() { asm volatile("cp.async.commit_group;" ::: "memory"); }
__device__ __forceinline__ void cpa_wait0()  { asm volatile("cp.async.wait_group 0;" ::: "memory"); }
__device__ __forceinline__ void cpa_wait1()  { asm volatile("cp.async.wait_group 1;" ::: "memory"); }
__device__ __forceinline__ void cpa_wait2()  { asm volatile("cp.async.wait_group 2;" ::: "memory"); }

// ---------------- prep ----------------
__global__ void __launch_bounds__(256) k_prep(const float* __restrict__ f) {
    __shared__ float t[32][33];
    int n0 = blockIdx.x * 32, d0 = blockIdx.y * 32;
    int tx = threadIdx.x, ty = threadIdx.y;
    #pragma unroll
    for (int i = ty; i < 32; i += 8) {
        float v = f[(size_t)(n0 + i) * DF + d0 + tx];
        t[i][tx] = v;
        g_cat[(size_t)(n0 + i) * KCAT + d0 + tx] = __float2half(v);
    }
    __syncthreads();
    #pragma unroll
    for (int i = ty; i < 32; i += 8)
        g_ftT[(size_t)(d0 + i) * NN + n0 + tx] = __float2half(t[tx][i]);
}

__global__ void __launch_bounds__(256) k_wconv(const float* __restrict__ W) {
    int i = blockIdx.x * 256 + threadIdx.x;
    g_w[i] = __float2half(W[i]);
}

// ================= k_main: split-K slice GEMM (frozen R15) =================
__global__ void __launch_bounds__(512, 1) k_main(const float* __restrict__ adj) {
    extern __shared__ char sm[];
    __half* Abuf = (__half*)sm;                // [2][128][72]
    __half* Bbuf = (__half*)(sm + OFF_BM);     // [3][256][72]

    const int tid = threadIdx.x;
    const int lane = tid & 31;
    const int wid = tid >> 5;
    const int wm = wid >> 2, wn = wid & 3;     // 4x4 warps, 32x64 tiles
    const int m0 = blockIdx.x * 128;
    const int slc = blockIdx.y;                // 0..7
    const int K0 = slc * SLC_ITERS;
    const uint32_t b_u32 = smem_u32(Bbuf);

    wmma::fragment<wmma::accumulator, 16, 16, 16, __half> acc[2][4];
    #pragma unroll
    for (int mi = 0; mi < 2; mi++)
        #pragma unroll
        for (int ni = 0; ni < 4; ni++)
            wmma::fill_fragment(acc[mi][ni], __float2half(0.0f));

    float rowacc[4] = {0.f, 0.f, 0.f, 0.f};
    float4 va[4];

    auto ldgA = [&](int it) {
        int k0 = (K0 + it) * 64;
        #pragma unroll
        for (int j = 0; j < 4; j++) {
            int idx = tid + j * 512;
            int row = idx >> 4, c4 = idx & 15;
            va[j] = *(const float4*)(adj + (size_t)(m0 + row) * NN + k0 + c4 * 4);
        }
    };
    auto stsA = [&](int buf) {
        __half* At = Abuf + buf * 128 * ASTM;
        #pragma unroll
        for (int j = 0; j < 4; j++) {
            int idx = tid + j * 512;
            int row = idx >> 4, c4 = idx & 15;
            float4 v = va[j];
            rowacc[j] += (v.x + v.y) + (v.z + v.w);
            __half2 h0 = __floats2half2_rn(v.x, v.y);
            __half2 h1 = __floats2half2_rn(v.z, v.w);
            uint2 u;
            u.x = *(uint32_t*)&h0;
            u.y = *(uint32_t*)&h1;
            *(uint2*)(At + row * ASTM + c4 * 4) = u;
        }
    };
    auto cpaB = [&](int buf, int it) {
        int k0 = (K0 + it) * 64;
        uint32_t b0 = b_u32 + buf * B_STG;
        #pragma unroll
        for (int j = 0; j < 4; j++) {
            int idx = tid + j * 512;
            int row = idx >> 3, c16 = idx & 7;
            cpa16(b0 + (row * ASTM + c16 * 8) * 2, g_ftT + (size_t)row * NN + k0 + c16 * 8);
        }
    };

    ldgA(0);
    stsA(0);
    ldgA(1);
    cpaB(0, 0); cpa_commit();
    cpaB(1, 1); cpa_commit();

    constexpr int NK = SLC_ITERS;  // 32
    int bs = 0, bs2 = 2;

    #pragma unroll 1
    for (int it = 0; it < NK; ++it) {
        int cur = it & 1;
        cpa_wait1();
        __syncthreads();

        if (it + 1 < NK) stsA(cur ^ 1);
        if (it + 2 < NK) {
            ldgA(it + 2);
            cpaB(bs2, it + 2);
        }
        cpa_commit();

        const __half* At = Abuf + cur * 128 * ASTM;
        const __half* Bt = Bbuf + bs * 256 * ASTM;
        #pragma unroll
        for (int ks = 0; ks < 4; ++ks) {
            wmma::fragment<wmma::matrix_a, 16, 16, 16, __half, wmma::row_major> af[2];
            #pragma unroll
            for (int mi = 0; mi < 2; mi++)
                wmma::load_matrix_sync(af[mi], At + (wm * 32 + mi * 16) * ASTM + ks * 16, ASTM);
            #pragma unroll
            for (int ni = 0; ni < 4; ni++) {
                wmma::fragment<wmma::matrix_b, 16, 16, 16, __half, wmma::col_major> bf;
                wmma::load_matrix_sync(bf, Bt + (wn * 64 + ni * 16) * ASTM + ks * 16, ASTM);
                #pragma unroll
                for (int mi = 0; mi < 2; mi++)
                    wmma::mma_sync(acc[mi][ni], af[mi], bf, acc[mi][ni]);
            }
        }
        bs = (bs == 2) ? 0 : bs + 1;
        bs2 = (bs2 == 2) ? 0 : bs2 + 1;
    }
    cpa_wait0();

    // partial rowsum -> g_rs
    #pragma unroll
    for (int j = 0; j < 4; j++) {
        float s = rowacc[j];
        s += __shfl_xor_sync(0xFFFFFFFFu, s, 1);
        s += __shfl_xor_sync(0xFFFFFFFFu, s, 2);
        s += __shfl_xor_sync(0xFFFFFFFFu, s, 4);
        s += __shfl_xor_sync(0xFFFFFFFFu, s, 8);
        int row = (tid + j * 512) >> 4;
        if ((lane & 15) == 0) g_rs[(size_t)slc * NN + m0 + row] = s;
    }

    // partial P -> g_part fp16 (direct fragment stores)
    __half* dst = g_part + ((size_t)slc * NN + m0) * DF;
    #pragma unroll
    for (int mi = 0; mi < 2; mi++)
        #pragma unroll
        for (int ni = 0; ni < 4; ni++)
            wmma::store_matrix_sync(dst + (wm * 32 + mi * 16) * DF + wn * 64 + ni * 16,
                                    acc[mi][ni], DF, wmma::mem_row_major);
}

// ================= fused reduce: srow in smem + 8-way partial sum -> g_cat neigh =================
// block = 256 threads handles 8 rows x 32 uint4-groups (8 halves each)
__global__ void __launch_bounds__(256) k_reduce() {
    __shared__ float siv[8];
    const int r0 = blockIdx.x * 8;
    const int t = threadIdx.x;

    if (t < 8) {  // srow for this block's 8 rows, fixed slice order (deterministic)
        float s = 0.f;
        #pragma unroll
        for (int sl = 0; sl < NSLC; sl++) s += g_rs[(size_t)sl * NN + r0 + t];
        siv[t] = 1.0f / (s + 1.0f);
    }
    __syncthreads();

    const int row = r0 + (t >> 5);
    const int g = t & 31;                       // 32 groups of 8 halves = 256 cols
    float s[8] = {0.f, 0.f, 0.f, 0.f, 0.f, 0.f, 0.f, 0.f};
    #pragma unroll
    for (int sl = 0; sl < NSLC; sl++) {
        uint4 u = *(const uint4*)(g_part + ((size_t)sl * NN + row) * DF + g * 8);
        __half2 a = *(__half2*)&u.x, b = *(__half2*)&u.y;
        __half2 c = *(__half2*)&u.z, d = *(__half2*)&u.w;
        s[0] += __half2float(__low2half(a)); s[1] += __half2float(__high2half(a));
        s[2] += __half2float(__low2half(b)); s[3] += __half2float(__high2half(b));
        s[4] += __half2float(__low2half(c)); s[5] += __half2float(__high2half(c));
        s[6] += __half2float(__low2half(d)); s[7] += __half2float(__high2half(d));
    }
    float iv = siv[t >> 5];
    __half2 h0 = __floats2half2_rn(s[0] * iv, s[1] * iv);
    __half2 h1 = __floats2half2_rn(s[2] * iv, s[3] * iv);
    __half2 h2 = __floats2half2_rn(s[4] * iv, s[5] * iv);
    __half2 h3 = __floats2half2_rn(s[6] * iv, s[7] * iv);
    uint4 o;
    o.x = *(uint32_t*)&h0; o.y = *(uint32_t*)&h1;
    o.z = *(uint32_t*)&h2; o.w = *(uint32_t*)&h3;
    *(uint4*)(g_cat + (size_t)row * KCAT + 256 + g * 8) = o;
}

// ================= k_out: BM=64, 256 threads, 2 CTAs/SM (frozen R13) =================
__global__ void __launch_bounds__(256, 2) k_out(float* __restrict__ out) {
    extern __shared__ char sm[];
    __half* Abuf = (__half*)sm;                // [4][64][40]
    __half* Bbuf = (__half*)(sm + OFF_BO);     // [4][256][40]
    float*  stage = (float*)sm;                // epilogue reuse [64][68]

    const int tid = threadIdx.x;
    const int wid = tid >> 5;
    const int wm = wid >> 2, wn = wid & 3;
    const int m0 = blockIdx.x * 64;
    const uint32_t a_u32 = smem_u32(Abuf);
    const uint32_t b_u32 = smem_u32(Bbuf);

    wmma::fragment<wmma::accumulator, 16, 16, 16, float> acc[2][4];
    #pragma unroll
    for (int mi = 0; mi < 2; mi++)
        #pragma unroll
        for (int ni = 0; ni < 4; ni++)
            wmma::fill_fragment(acc[mi][ni], 0.0f);

    auto loadTile = [&](int slot, int it) {
        int k0 = it * 32;
        uint32_t a0 = a_u32 + slot * AO_STG;
        uint32_t b0 = b_u32 + slot * BO_STG;
        {
            int row = tid >> 2, c8 = tid & 3;
            cpa16(a0 + (row * AST + c8 * 8) * 2, g_cat + (size_t)(m0 + row) * KCAT + k0 + c8 * 8);
        }
        #pragma unroll
        for (int j = 0; j < 4; j++) {
            int idx = tid + j * 256;
            int row = idx >> 2, c8 = idx & 3;
            cpa16(b0 + (row * AST + c8 * 8) * 2, g_w + (size_t)row * KCAT + k0 + c8 * 8);
        }
    };

    loadTile(0, 0); cpa_commit();
    loadTile(1, 1); cpa_commit();
    loadTile(2, 2); cpa_commit();

    constexpr int NK = KCAT / 32;  // 16
    #pragma unroll 1
    for (int it = 0; it < NK; ++it) {
        int cur = it & 3;
        cpa_wait2();
        __syncthreads();

        if (it + 3 < NK) { loadTile((it + 3) & 3, it + 3); cpa_commit(); }

        const __half* At = Abuf + cur * 64 * AST;
        const __half* Bt = Bbuf + cur * 256 * AST;
        #pragma unroll
        for (int ks = 0; ks < 2; ++ks) {
            wmma::fragment<wmma::matrix_a, 16, 16, 16, __half, wmma::row_major> af[2];
            #pragma unroll
            for (int mi = 0; mi < 2; mi++)
                wmma::load_matrix_sync(af[mi], At + (wm * 32 + mi * 16) * AST + ks * 16, AST);
            #pragma unroll
            for (int ni = 0; ni < 4; ni++) {
                wmma::fragment<wmma::matrix_b, 16, 16, 16, __half, wmma::col_major> bf;
                wmma::load_matrix_sync(bf, Bt + (wn * 64 + ni * 16) * AST + ks * 16, AST);
                #pragma unroll
                for (int mi = 0; mi < 2; mi++)
                    wmma::mma_sync(acc[mi][ni], af[mi], bf, acc[mi][ni]);
            }
        }
    }
    cpa_wait0();
    __syncthreads();

    #pragma unroll 1
    for (int p = 0; p < 4; p++) {
        if (wn == p) {
            #pragma unroll
            for (int mi = 0; mi < 2; mi++)
                #pragma unroll
                for (int ni = 0; ni < 4; ni++)
                    wmma::store_matrix_sync(stage + (wm * 32 + mi * 16) * SST + ni * 16,
                                            acc[mi][ni], SST, wmma::mem_row_major);
        }
        __syncthreads();
        #pragma unroll
        for (int j = 0; j < 16; j++) {
            int idx = tid + j * 256;
            int r = idx >> 6, c = idx & 63;
            out[(size_t)(m0 + r) * DF + p * 64 + c] = stage[r * SST + c];
        }
        __syncthreads();
    }
}

// ---------------- launch ----------------
extern "C" void kernel_launch(void* const* d_in, const int* in_sizes, int n_in,
                              void* d_out, int out_size) {
    const float* features = nullptr;
    const float* adj = nullptr;
    const float* W = nullptr;
    for (int i = 0; i < n_in; i++) {
        if (in_sizes[i] == NN * NN) adj = (const float*)d_in[i];
        else if (in_sizes[i] == NN * DF) features = (const float*)d_in[i];
        else if (in_sizes[i] == DF * KCAT) W = (const float*)d_in[i];
    }
    float* out = (float*)d_out;

    cudaFuncSetAttribute(k_main, cudaFuncAttributeMaxDynamicSharedMemorySize, SMEM_MAIN);
    cudaFuncSetAttribute(k_out,  cudaFuncAttributeMaxDynamicSharedMemorySize, SMEM_OUT);

    k_prep<<<dim3(NN / 32, DF / 32), dim3(32, 8)>>>(features);
    k_wconv<<<(DF * KCAT) / 256, 256>>>(W);
    k_main<<<dim3(NN / 128, NSLC), 512, SMEM_MAIN>>>(adj);
    k_reduce<<<NN / 8, 256>>>();
    k_out<<<NN / 64, 256, SMEM_OUT>>>(out);
}